// round 14
// baseline (speedup 1.0000x reference)
#include <cuda_runtime.h>
#include <math.h>
#include <float.h>
#include <stdint.h>

// Problem constants (fixed by the dataset)
#define S_   7
#define B_   2
#define C_   80
#define NGT  32
#define BT_  8192
#define CELLF 90                    // B*5 + C
#define NCELLS (BT_ * S_ * S_)      // 401408
#define NBOX   (NCELLS * B_)        // 802816
#define NGTS   (BT_ * NGT)          // 262144

#define NTHR 128
#define NBLK (BT_ / 2)              // 4096 blocks, one 2-item pair each
#define PAIRC 98                    // cells per pair
#define SLABF (PAIRC * CELLF)       // 8820 floats
#define SLABB (SLABF * 4)           // 35280 bytes (16B multiple)
#define NCHUNK (SLABB / 16)         // 2205 16B chunks
#define NWARP (NTHR / 32)           // 4

// Per-block partial sums: [coord, obj, posconf_sq, cls, npos, noobj_all]
__device__ double g_part[NBLK][6];
__device__ unsigned int g_count = 0;

__device__ __forceinline__ float sigmoidf_(float x) {
    return 1.0f / (1.0f + __expf(-x));
}

__device__ __forceinline__ uint32_t smem_u32(const void* p) {
    uint32_t a;
    asm("{ .reg .u64 t; cvta.to.shared.u64 t, %1; cvt.u32.u64 %0, t; }"
        : "=r"(a) : "l"(p));
    return a;
}

__device__ __forceinline__ void cp16(uint32_t dst, const void* src) {
    asm volatile("cp.async.cg.shared.global [%0], [%1], 16;"
                 :: "r"(dst), "l"(src) : "memory");
}

__global__ void __launch_bounds__(NTHR, 6)
yolo_loss_cellstream(const float* __restrict__ preds,
                     const float* __restrict__ gt_boxes,
                     const int* __restrict__ gt_labels,
                     const unsigned char* __restrict__ gt_valid,
                     float* __restrict__ out)
{
    __shared__ __align__(16) float slab[SLABF];     // 35,280 B
    __shared__ float ssum[PAIRC][2];
    __shared__ double shred[NWARP][6];

    const int tid  = threadIdx.x;
    const int lane = tid & 31;
    const int wid  = tid >> 5;
    const unsigned FULL = 0xffffffffu;

    // ---- issue the coalesced slab copy (all threads) ----
    {
        const uint32_t sa = smem_u32(slab);
        const char* src = (const char*)preds + (size_t)blockIdx.x * SLABB;
        #pragma unroll 5
        for (int i = tid; i < NCHUNK; i += NTHR)
            cp16(sa + (uint32_t)i * 16u, src + (size_t)i * 16u);
        asm volatile("cp.async.commit_group;" ::: "memory");
    }

    // ---- GT metadata loads overlap the copy (threads 0..63, coalesced) ----
    const int il = tid >> 5;            // item within pair (for tid<64)
    const int g  = tid & 31;            // GT within item
    float4 gb = make_float4(0.f, 0.f, 0.f, 0.f);
    int label = 0; float mval = 0.f;
    if (tid < 64) {
        const int t = (blockIdx.x * 2 + il) * NGT + g;
        mval  = (__ldg(gt_valid + t) != 0) ? 1.0f : 0.0f;
        gb    = __ldg((const float4*)gt_boxes + t);
        label = __ldg(gt_labels + t);
    }

    asm volatile("cp.async.wait_group 0;" ::: "memory");
    __syncthreads();

    float coord = 0.f, obj = 0.f, posconf = 0.f, clsl = 0.f, npos = 0.f, noobj = 0.f;

    // ================= thread-per-cell: conf + softmax sums =================
    if (tid < PAIRC) {
        const float2* row = (const float2*)(slab + tid * CELLF);   // 90 floats, 8B-aligned

        // conf values: positions 4 (row[2].x) and 9 (row[4].y)
        const float ca = sigmoidf_(row[2].x);
        const float cb = sigmoidf_(row[4].y);
        noobj = ca * ca + cb * cb;

        // class logits: positions 10..89 = float2 slots 5..44
        float s0 = 0.f, s1 = 0.f, q0 = 0.f, q1 = 0.f;
        #pragma unroll
        for (int i = 5; i < 45; i++) {
            const float2 v = row[i];
            const float ea = __expf(v.x);
            const float eb = __expf(v.y);
            s0 += ea; q0 += ea * ea;
            s1 += eb; q1 += eb * eb;
        }
        ssum[tid][0] = s0 + s1;
        ssum[tid][1] = q0 + q1;
    }
    __syncthreads();

    // ================= thread-per-GT tail (threads 0..63), all from smem =================
    if (tid < 64) {
        const float x1 = gb.x, y1 = gb.y, x2 = gb.z, y2 = gb.w;
        const float cx = (x1 + x2) * 0.5f;
        const float cy = (y1 + y2) * 0.5f;
        const float w  = fmaxf(x2 - x1, 1e-6f);
        const float h  = fmaxf(y2 - y1, 1e-6f);
        const int gi = min(max((int)floorf(cx * (float)S_), 0), S_ - 1);
        const int gj = min(max((int)floorf(cy * (float)S_), 0), S_ - 1);
        const int lc = il * (S_ * S_) + gj * S_ + gi;      // local cell in slab

        const float s  = ssum[lc][0];
        const float sq = ssum[lc][1];
        const float el = __expf(slab[lc * CELLF + 10 + label]);
        const float inv = 1.0f / s;
        const float cls_term = sq * inv * inv - 2.0f * el * inv + 1.0f;

        float bx[10];
        const float2* bp = (const float2*)(slab + lc * CELLF);
        #pragma unroll
        for (int j = 0; j < 5; j++) { bx[2*j] = bp[j].x; bx[2*j+1] = bp[j].y; }

        const float area_g = (x2 - x1) * (y2 - y1);
        float iou[2], sxk[2], syk[2], twk[2], thk[2], tok[2];
        #pragma unroll
        for (int k = 0; k < 2; k++) {
            const float tx = bx[k*5+0], ty = bx[k*5+1];
            const float tw = bx[k*5+2], th = bx[k*5+3];
            const float sx = sigmoidf_(tx);
            const float sy = sigmoidf_(ty);
            const float pw = tw * tw, ph = th * th;
            const float px = (sx + (float)gi) * (1.0f / S_);
            const float py = (sy + (float)gj) * (1.0f / S_);
            const float px1 = px - 0.5f * pw, px2v = px + 0.5f * pw;
            const float py1 = py - 0.5f * ph, py2v = py + 0.5f * ph;
            const float iw = fmaxf(0.f, fminf(px2v, x2) - fmaxf(px1, x1));
            const float ih = fmaxf(0.f, fminf(py2v, y2) - fmaxf(py1, y1));
            const float inter = iw * ih;
            iou[k] = inter / (pw * ph + area_g - inter + 1e-6f);
            sxk[k] = sx; syk[k] = sy; twk[k] = tw; thk[k] = th; tok[k] = bx[k*5+4];
        }
        const int   best = (iou[1] > iou[0]) ? 1 : 0;
        const float iou_best = fmaxf(iou[0], iou[1]);

        const float so  = sigmoidf_(tok[best]);
        const float tgx = cx * (float)S_ - (float)gi;
        const float tgy = cy * (float)S_ - (float)gj;
        const float tgw = sqrtf(w), tgh = sqrtf(h);
        const float dx = sxk[best] - tgx, dy = syk[best] - tgy;
        const float dw = twk[best] - tgw, dh = thk[best] - tgh;
        const float dob = so - iou_best;

        coord   = mval * (dx*dx + dy*dy + dw*dw + dh*dh);
        obj     = mval * dob * dob;
        posconf = mval * so * so;
        npos    = mval;
        clsl    = mval * cls_term;
    }

    // ================= Block reduction -> g_part =================
    float vals[6] = {coord, obj, posconf, clsl, npos, noobj};
    #pragma unroll
    for (int j = 0; j < 6; j++) {
        #pragma unroll
        for (int o = 16; o; o >>= 1)
            vals[j] += __shfl_xor_sync(FULL, vals[j], o);
    }
    if (lane == 0) {
        #pragma unroll
        for (int j = 0; j < 6; j++) shred[wid][j] = (double)vals[j];
    }
    __syncthreads();
    if (tid < 6) {
        double acc = 0.0;
        #pragma unroll
        for (int wI = 0; wI < NWARP; wI++) acc += shred[wI][tid];
        g_part[blockIdx.x][tid] = acc;
    }

    // ================= Grid-wide finalize: last block reduces =================
    __shared__ bool is_last;
    __threadfence();
    if (tid == 0) {
        const unsigned prev = atomicAdd(&g_count, 1u);
        is_last = (prev == (unsigned)(NBLK - 1));
        if (is_last) g_count = 0u;          // reset for next graph replay
    }
    __syncthreads();
    if (!is_last) return;

    double a[6] = {0, 0, 0, 0, 0, 0};
    for (int bb = tid; bb < NBLK; bb += NTHR) {
        #pragma unroll
        for (int j = 0; j < 6; j++) a[j] += __ldcg(&g_part[bb][j]);
    }
    #pragma unroll
    for (int j = 0; j < 6; j++) {
        #pragma unroll
        for (int o = 16; o; o >>= 1)
            a[j] += __shfl_xor_sync(FULL, a[j], o);
    }
    if (lane == 0) {
        #pragma unroll
        for (int j = 0; j < 6; j++) shred[wid][j] = a[j];
    }
    __syncthreads();
    if (tid == 0) {
        double tt[6];
        #pragma unroll
        for (int j = 0; j < 6; j++) {
            tt[j] = 0.0;
            for (int wI = 0; wI < NWARP; wI++) tt[j] += shred[wI][j];
        }
        const double nposd = fmax(tt[4], 1.0);
        const double nneg  = fmax((double)NBOX - tt[4], 1.0);
        const double ncell = fmax(tt[4], 1.0);   // GT cells are distinct per batch item
        const double loss = 5.0 * tt[0] / nposd          // LC * coord
                          + tt[1] / nposd                // obj
                          + 0.5 * (tt[5] - tt[2]) / nneg // LN * noobj (all - positive)
                          + tt[3] / ncell;               // cls
        *out = (float)loss;
    }
}

extern "C" void kernel_launch(void* const* d_in, const int* in_sizes, int n_in,
                              void* d_out, int out_size)
{
    const float*         preds     = (const float*)d_in[0];
    const float*         gt_boxes  = (const float*)d_in[1];
    const int*           gt_labels = (const int*)d_in[2];
    const unsigned char* gt_valid  = (const unsigned char*)d_in[3];
    float* out = (float*)d_out;

    yolo_loss_cellstream<<<NBLK, NTHR>>>(preds, gt_boxes, gt_labels, gt_valid, out);
}

// round 15
// speedup vs baseline: 1.2482x; 1.2482x over previous
#include <cuda_runtime.h>
#include <math.h>
#include <float.h>

// Problem constants (fixed by the dataset)
#define S_   7
#define B_   2
#define C_   80
#define NGT  32
#define BT_  8192
#define CELLF 90                    // B*5 + C
#define NCELLS (BT_ * S_ * S_)      // 401408
#define NBOX   (NCELLS * B_)        // 802816
#define NGTS   (BT_ * NGT)          // 262144

#define NTHR 128
#define NBLK 4096                   // 524288 threads = 2 per GT
#define NWARP (NTHR / 32)           // 4

// Per-block partial sums: [coord, obj, posconf_sq, cls, npos, noobj_all]
__device__ double g_part[NBLK][6];
__device__ unsigned int g_count = 0;

__device__ __forceinline__ float sigmoidf_(float x) {
    return 1.0f / (1.0f + __expf(-x));
}

__global__ void __launch_bounds__(NTHR, 9)
yolo_loss_pair4(const float* __restrict__ preds,
                const float* __restrict__ gt_boxes,
                const int* __restrict__ gt_labels,
                const unsigned char* __restrict__ gt_valid,
                float* __restrict__ out)
{
    const int tid  = threadIdx.x;
    const int lane = tid & 31;
    const int wid  = tid >> 5;
    const int tg   = blockIdx.x * NTHR + tid;   // global thread id
    const int gt   = tg >> 1;                   // GT index (2 threads per GT)
    const int half = tg & 1;                    // 0: vec 0..11 (box + cls 10..45); 1: vec 11..22 (cls 46..89)
    const unsigned FULL = 0xffffffffu;

    float coord = 0.f, obj = 0.f, posconf = 0.f, clsl = 0.f, npos = 0.f, noobj = 0.f;

    // ===== Phase 2 conf loads hoisted (<=1 cell per thread) =====
    float pa = 0.f, pb = 0.f;
    const bool hasC = (tg < NCELLS);
    if (hasC) {
        pa = __ldg(preds + (size_t)tg * CELLF + 4);
        pb = __ldg(preds + (size_t)tg * CELLF + 9);
    }

    // ===== GT metadata (lane pairs hit the same addresses -> L1 broadcast) =====
    const float mval = (__ldg(gt_valid + gt) != 0) ? 1.0f : 0.0f;
    const float4 gb  = __ldg((const float4*)gt_boxes + gt);
    const int   label = __ldg(gt_labels + gt);

    const float x1 = gb.x, y1 = gb.y, x2 = gb.z, y2 = gb.w;
    const float cx = (x1 + x2) * 0.5f;
    const float cy = (y1 + y2) * 0.5f;
    const int gi = min(max((int)floorf(cx * (float)S_), 0), S_ - 1);
    const int gj = min(max((int)floorf(cy * (float)S_), 0), S_ - 1);

    const int  b       = gt >> 5;                      // gt / NGT
    const int  cellIdx = b * (S_ * S_) + gj * S_ + gi;
    const float* cell  = preds + (size_t)cellIdx * CELLF;

    // 16B-aligned vec4 view (off trick, proven since R3)
    const int off = (cellIdx & 1) << 1;                // 0 or 2 floats
    const float4* vb = (const float4*)(cell - off);

    // label-logit scalar gather (even lane only; overlaps loads)
    float cl = 0.f;
    if (half == 0) cl = __ldg(cell + 10 + label);

    // ===== masked softmax over my 12 vec4s =====
    // even: vec 0..11 -> class positions 10..45 (36 values)
    // odd : vec 11..22 -> class positions 46..89 (44 values)
    const int      jbase = 11 * half;
    const unsigned lob   = 10u + 36u * (unsigned)half;  // 10 or 46
    const unsigned rng   = half ? 44u : 36u;

    float s = 0.f, sq = 0.f;
    float p[12];                                         // even lane: loaded positions -off..11-off

    #pragma unroll
    for (int c = 0; c < 3; c++) {
        float4 v[4];
        #pragma unroll
        for (int k = 0; k < 4; k++)
            v[k] = __ldg(vb + jbase + c * 4 + k);

        if (c == 0) {   // stash first 3 vec4s for box extraction (even lane uses)
            p[0]=v[0].x; p[1]=v[0].y; p[2]=v[0].z;  p[3]=v[0].w;
            p[4]=v[1].x; p[5]=v[1].y; p[6]=v[1].z;  p[7]=v[1].w;
            p[8]=v[2].x; p[9]=v[2].y; p[10]=v[2].z; p[11]=v[2].w;
        }

        #pragma unroll
        for (int k = 0; k < 4; k++) {
            const int pos0 = 4 * (jbase + c * 4 + k) - off;
            const float va[4] = {v[k].x, v[k].y, v[k].z, v[k].w};
            #pragma unroll
            for (int e = 0; e < 4; e++) {
                const float ex = __expf(va[e]);
                const float em = ((unsigned)(pos0 + e - (int)lob) < rng) ? ex : 0.f;
                s  += em;
                sq += em * em;
            }
        }
    }

    // combine the two halves (2 shuffles total per GT)
    s  += __shfl_xor_sync(FULL, s,  1);
    sq += __shfl_xor_sync(FULL, sq, 1);

    // phase-2 math (loads long arrived)
    if (hasC) {
        const float sa = sigmoidf_(pa), sb = sigmoidf_(pb);
        noobj = sa * sa + sb * sb;
    }

    // ===== even-lane tail: cls term + IoU + coord/obj =====
    if (half == 0) {
        float bx[10];
        #pragma unroll
        for (int j = 0; j < 10; j++) bx[j] = (off != 0) ? p[j + 2] : p[j];

        const float el  = __expf(cl);
        const float inv = 1.0f / s;
        const float cls_term = sq * inv * inv - 2.0f * el * inv + 1.0f;

        const float w = fmaxf(x2 - x1, 1e-6f);
        const float h = fmaxf(y2 - y1, 1e-6f);
        const float area_g = (x2 - x1) * (y2 - y1);

        float iou[2], sxk[2], syk[2], twk[2], thk[2], tok[2];
        #pragma unroll
        for (int k = 0; k < 2; k++) {
            const float tx = bx[k*5+0], ty = bx[k*5+1];
            const float tw = bx[k*5+2], th = bx[k*5+3];
            const float sx = sigmoidf_(tx);
            const float sy = sigmoidf_(ty);
            const float pw = tw * tw, ph = th * th;
            const float px = (sx + (float)gi) * (1.0f / S_);
            const float py = (sy + (float)gj) * (1.0f / S_);
            const float px1 = px - 0.5f * pw, px2v = px + 0.5f * pw;
            const float py1 = py - 0.5f * ph, py2v = py + 0.5f * ph;
            const float iw = fmaxf(0.f, fminf(px2v, x2) - fmaxf(px1, x1));
            const float ih = fmaxf(0.f, fminf(py2v, y2) - fmaxf(py1, y1));
            const float inter = iw * ih;
            iou[k] = inter / (pw * ph + area_g - inter + 1e-6f);
            sxk[k] = sx; syk[k] = sy; twk[k] = tw; thk[k] = th; tok[k] = bx[k*5+4];
        }
        const int   best = (iou[1] > iou[0]) ? 1 : 0;
        const float iou_best = fmaxf(iou[0], iou[1]);

        const float so  = sigmoidf_(tok[best]);
        const float tgx = cx * (float)S_ - (float)gi;
        const float tgy = cy * (float)S_ - (float)gj;
        const float tgw = sqrtf(w), tgh = sqrtf(h);
        const float dx = sxk[best] - tgx, dy = syk[best] - tgy;
        const float dw = twk[best] - tgw, dh = thk[best] - tgh;
        const float dob = so - iou_best;

        coord   = mval * (dx*dx + dy*dy + dw*dw + dh*dh);
        obj     = mval * dob * dob;
        posconf = mval * so * so;
        npos    = mval;
        clsl    = mval * cls_term;
    }

    // ================= Block reduction -> g_part =================
    float vals[6] = {coord, obj, posconf, clsl, npos, noobj};
    #pragma unroll
    for (int j = 0; j < 6; j++) {
        #pragma unroll
        for (int o = 16; o; o >>= 1)
            vals[j] += __shfl_xor_sync(FULL, vals[j], o);
    }
    __shared__ double sh[NWARP][6];
    if (lane == 0) {
        #pragma unroll
        for (int j = 0; j < 6; j++) sh[wid][j] = (double)vals[j];
    }
    __syncthreads();
    if (tid < 6) {
        double acc = 0.0;
        #pragma unroll
        for (int wI = 0; wI < NWARP; wI++) acc += sh[wI][tid];
        g_part[blockIdx.x][tid] = acc;
    }

    // ================= Grid-wide finalize: last block reduces =================
    __shared__ bool is_last;
    __threadfence();
    if (tid == 0) {
        const unsigned prev = atomicAdd(&g_count, 1u);
        is_last = (prev == (unsigned)(NBLK - 1));
        if (is_last) g_count = 0u;          // reset for next graph replay
    }
    __syncthreads();
    if (!is_last) return;

    double a[6] = {0, 0, 0, 0, 0, 0};
    for (int bb = tid; bb < NBLK; bb += NTHR) {
        #pragma unroll
        for (int j = 0; j < 6; j++) a[j] += __ldcg(&g_part[bb][j]);
    }
    #pragma unroll
    for (int j = 0; j < 6; j++) {
        #pragma unroll
        for (int o = 16; o; o >>= 1)
            a[j] += __shfl_xor_sync(FULL, a[j], o);
    }
    __shared__ double shf[NWARP][6];
    if (lane == 0) {
        #pragma unroll
        for (int j = 0; j < 6; j++) shf[wid][j] = a[j];
    }
    __syncthreads();
    if (tid == 0) {
        double tt[6];
        #pragma unroll
        for (int j = 0; j < 6; j++) {
            tt[j] = 0.0;
            for (int wI = 0; wI < NWARP; wI++) tt[j] += shf[wI][j];
        }
        const double nposd = fmax(tt[4], 1.0);
        const double nneg  = fmax((double)NBOX - tt[4], 1.0);
        const double ncell = fmax(tt[4], 1.0);   // GT cells are distinct per batch item
        const double loss = 5.0 * tt[0] / nposd          // LC * coord
                          + tt[1] / nposd                // obj
                          + 0.5 * (tt[5] - tt[2]) / nneg // LN * noobj (all - positive)
                          + tt[3] / ncell;               // cls
        *out = (float)loss;
    }
}

extern "C" void kernel_launch(void* const* d_in, const int* in_sizes, int n_in,
                              void* d_out, int out_size)
{
    const float*         preds     = (const float*)d_in[0];
    const float*         gt_boxes  = (const float*)d_in[1];
    const int*           gt_labels = (const int*)d_in[2];
    const unsigned char* gt_valid  = (const unsigned char*)d_in[3];
    float* out = (float*)d_out;

    yolo_loss_pair4<<<NBLK, NTHR>>>(preds, gt_boxes, gt_labels, gt_valid, out);
}